// round 1
// baseline (speedup 1.0000x reference)
#include <cuda_runtime.h>
#include <math.h>

#define HH 128
#define WW 128
#define CC 64
#define BB 8
#define HW (HH*WW)

// scratch (device globals — no allocations allowed)
__device__ float g_off[BB*18*HW];     // offset channels (om[:, :18])
__device__ float g_mask[BB*9*HW];     // sigmoid(om[:, 18:])
__device__ float g_wt[9*64*64];       // w_dcn transposed to [k][c][oc]
__device__ float g_stats[2*BB*CC];    // mean, rstd per (b, oc)

// ---------------------------------------------------------------------------
// Kernel W: transpose w_dcn [oc][c][3][3] -> g_wt [k][c][oc]
// ---------------------------------------------------------------------------
__global__ void k_wt(const float* __restrict__ w_dcn) {
    int idx = blockIdx.x * 256 + threadIdx.x;
    if (idx < 64*64*9) {
        int oc = idx / (64*9);
        int r  = idx % (64*9);
        int c  = r / 9;
        int k  = r % 9;
        g_wt[(k*64 + c)*64 + oc] = w_dcn[idx];
    }
}

// ---------------------------------------------------------------------------
// Kernel 1: offset conv (3x3 SAME, 64 -> 27 channels) + bias + sigmoid(mask)
// tile 64w x 16h, 256 threads, thread = 4 consecutive px in one row
// ---------------------------------------------------------------------------
#define K1_SMEM ((16*18*66 + 27*64*9 + 32) * 4)

__global__ void __launch_bounds__(256, 1)
k_off(const float* __restrict__ x, const float* __restrict__ w_off,
      const float* __restrict__ b_off) {
    extern __shared__ float sm[];
    float* s_x = sm;                    // [16][18][66]
    float* s_w = sm + 16*18*66;         // [27][64][9]
    float* s_b = s_w + 27*64*9;         // [27]

    int t = threadIdx.x;
    int b   = blockIdx.z;
    int gi0 = blockIdx.y * 16;
    int gj0 = blockIdx.x * 64;

    for (int i = t; i < 27*64*9; i += 256) s_w[i] = w_off[i];
    if (t < 27) s_b[t] = b_off[t];

    int tx = t & 15, ty = t >> 4;       // px row = gi0+ty, cols gj0 + tx*4 .. +3
    float acc[27][4];
    #pragma unroll
    for (int o = 0; o < 27; o++)
        #pragma unroll
        for (int q = 0; q < 4; q++) acc[o][q] = 0.f;

    for (int cc = 0; cc < 4; cc++) {
        __syncthreads();
        // load x chunk [16 ch][18 rows][66 cols] with halo, zero-padded
        for (int i = t; i < 16*18*66; i += 256) {
            int ci = i / (18*66);
            int rr = (i / 66) % 18;
            int cl = i % 66;
            int gi = gi0 - 1 + rr, gj = gj0 - 1 + cl;
            float v = 0.f;
            if (gi >= 0 && gi < HH && gj >= 0 && gj < WW)
                v = x[(((size_t)b*CC + cc*16 + ci)*HH + gi)*WW + gj];
            s_x[i] = v;
        }
        __syncthreads();

        #pragma unroll 1
        for (int ci = 0; ci < 16; ci++) {
            float xv[3][6];
            const float* xp = &s_x[ci*18*66 + ty*66 + tx*4];
            #pragma unroll
            for (int ky = 0; ky < 3; ky++)
                #pragma unroll
                for (int s = 0; s < 6; s++)
                    xv[ky][s] = xp[ky*66 + s];
            int c = cc*16 + ci;
            const float* wc = &s_w[c*9];
            #pragma unroll
            for (int o = 0; o < 27; o++) {
                const float* w9 = wc + o*576;   // (o*64 + c)*9
                #pragma unroll
                for (int ky = 0; ky < 3; ky++) {
                    float w0 = w9[ky*3+0], w1 = w9[ky*3+1], w2 = w9[ky*3+2];
                    #pragma unroll
                    for (int q = 0; q < 4; q++)
                        acc[o][q] += xv[ky][q]*w0 + xv[ky][q+1]*w1 + xv[ky][q+2]*w2;
                }
            }
        }
    }

    int gi = gi0 + ty, gj = gj0 + tx*4;
    #pragma unroll
    for (int o = 0; o < 27; o++) {
        float bo = s_b[o];
        float4 v = make_float4(acc[o][0]+bo, acc[o][1]+bo, acc[o][2]+bo, acc[o][3]+bo);
        if (o < 18) {
            *(float4*)&g_off[(((size_t)b*18 + o)*HH + gi)*WW + gj] = v;
        } else {
            v.x = 1.f/(1.f+expf(-v.x));
            v.y = 1.f/(1.f+expf(-v.y));
            v.z = 1.f/(1.f+expf(-v.z));
            v.w = 1.f/(1.f+expf(-v.w));
            *(float4*)&g_mask[(((size_t)b*9 + (o-18))*HH + gi)*WW + gj] = v;
        }
    }
}

// ---------------------------------------------------------------------------
// Kernel 2: deformable conv. Block = 64 px of one row (b, i, j0..j0+63),
// 256 threads. Per k-tap: compute sample params -> gather v[c][p] -> GEMM
// out[oc][p] += sum_c v[c][p] * w_k[c][oc]. Thread tile = 4oc x 4px.
// ---------------------------------------------------------------------------
__global__ void __launch_bounds__(256)
k_dcn(const float* __restrict__ x, float* __restrict__ out) {
    __shared__ float s_v[64][68];    // [c][p]
    __shared__ float s_w[64][68];    // [c][oc]
    __shared__ float s_wt[4][64];    // tap weights (mask+validity folded)
    __shared__ int   s_ad[4][64];    // tap addresses within one channel plane

    int t  = threadIdx.x;
    int b  = blockIdx.y;
    int i  = blockIdx.x >> 1;
    int j0 = (blockIdx.x & 1) << 6;
    int ocg = t >> 4, pg = t & 15;
    int oc0 = ocg << 2, p0 = pg << 2;

    float acc[16];
    #pragma unroll
    for (int q = 0; q < 16; q++) acc[q] = 0.f;

    const float* xb = x + (size_t)b * CC * HW;

    for (int k = 0; k < 9; k++) {
        if (t < 64) {
            int p = t, j = j0 + p;
            int ky = k/3 - 1, kx = k%3 - 1;
            float oy = g_off[(((size_t)b*18 + 2*k  )*HH + i)*WW + j];
            float ox = g_off[(((size_t)b*18 + 2*k+1)*HH + i)*WW + j];
            float m  = g_mask[(((size_t)b*9 + k)*HH + i)*WW + j];
            float ys = (float)(i + ky) + oy;
            float xs = (float)(j + kx) + ox;
            float y0 = floorf(ys), x0 = floorf(xs);
            float wy1 = ys - y0, wx1 = xs - x0;
            float wy0 = 1.f - wy1, wx0 = 1.f - wx1;
            #pragma unroll
            for (int tap = 0; tap < 4; tap++) {
                float yf = y0 + (float)(tap >> 1);
                float xf = x0 + (float)(tap & 1);
                bool val = (yf >= 0.f) && (yf < (float)HH) &&
                           (xf >= 0.f) && (xf < (float)WW);
                int yc = max(0, min(HH-1, (int)yf));
                int xc = max(0, min(WW-1, (int)xf));
                float wt = ((tap>>1) ? wy1 : wy0) * ((tap&1) ? wx1 : wx0) * m;
                s_wt[tap][p] = val ? wt : 0.f;
                s_ad[tap][p] = yc*WW + xc;
            }
        }
        // stage this tap's weights [c][oc] (coalesced from pre-transposed g_wt)
        {
            const float4* wk = (const float4*)(g_wt + k*4096);
            #pragma unroll
            for (int r = 0; r < 4; r++) {
                int idx4 = r*256 + t;
                int c = idx4 >> 4, o4 = idx4 & 15;
                *(float4*)&s_w[c][o4*4] = wk[idx4];
            }
        }
        __syncthreads();
        // bilinear gather into s_v[c][p]
        {
            int p = t & 63, cs = t >> 6;
            float w0 = s_wt[0][p], w1 = s_wt[1][p], w2 = s_wt[2][p], w3 = s_wt[3][p];
            int a0 = s_ad[0][p], a1 = s_ad[1][p], a2 = s_ad[2][p], a3 = s_ad[3][p];
            #pragma unroll 4
            for (int c = cs; c < 64; c += 4) {
                const float* xp = xb + c*HW;
                s_v[c][p] = w0*xp[a0] + w1*xp[a1] + w2*xp[a2] + w3*xp[a3];
            }
        }
        __syncthreads();
        // GEMM accumulate: 4oc x 4px per thread
        #pragma unroll 8
        for (int c = 0; c < 64; c++) {
            float4 wv = *(const float4*)&s_w[c][oc0];
            float4 vv = *(const float4*)&s_v[c][p0];
            acc[0]  += wv.x*vv.x; acc[1]  += wv.x*vv.y; acc[2]  += wv.x*vv.z; acc[3]  += wv.x*vv.w;
            acc[4]  += wv.y*vv.x; acc[5]  += wv.y*vv.y; acc[6]  += wv.y*vv.z; acc[7]  += wv.y*vv.w;
            acc[8]  += wv.z*vv.x; acc[9]  += wv.z*vv.y; acc[10] += wv.z*vv.z; acc[11] += wv.z*vv.w;
            acc[12] += wv.w*vv.x; acc[13] += wv.w*vv.y; acc[14] += wv.w*vv.z; acc[15] += wv.w*vv.w;
        }
        __syncthreads();
    }

    // b_dcn is skipped: instance norm (y - mean) cancels any per-channel bias.
    #pragma unroll
    for (int q = 0; q < 4; q++) {
        float4 v = make_float4(acc[q*4+0], acc[q*4+1], acc[q*4+2], acc[q*4+3]);
        *(float4*)&out[(((size_t)b*CC + oc0 + q)*HH + i)*WW + j0 + p0] = v;
    }
}

// ---------------------------------------------------------------------------
// Kernel 3: per-(b,oc) mean / rstd over 128x128
// ---------------------------------------------------------------------------
__global__ void k_stats(const float* __restrict__ y) {
    int bc = blockIdx.x;
    int t = threadIdx.x;
    const float4* p = (const float4*)(y + (size_t)bc * HW);
    float s = 0.f, ss = 0.f;
    #pragma unroll
    for (int r = 0; r < 16; r++) {
        float4 v = p[r*256 + t];
        s  += v.x + v.y + v.z + v.w;
        ss += v.x*v.x + v.y*v.y + v.z*v.z + v.w*v.w;
    }
    __shared__ float rs[256], rq[256];
    rs[t] = s; rq[t] = ss;
    __syncthreads();
    for (int st = 128; st > 0; st >>= 1) {
        if (t < st) { rs[t] += rs[t+st]; rq[t] += rq[t+st]; }
        __syncthreads();
    }
    if (t == 0) {
        float mean = rs[0] * (1.f/16384.f);
        float var  = rq[0] * (1.f/16384.f) - mean*mean;
        g_stats[bc] = mean;
        g_stats[BB*CC + bc] = rsqrtf(var + 1e-5f);
    }
}

// ---------------------------------------------------------------------------
// Kernel 4: normalize + relu, in place
// ---------------------------------------------------------------------------
__global__ void k_norm(float* __restrict__ y) {
    int bc = blockIdx.x;
    int t = threadIdx.x;
    float mean = g_stats[bc];
    float rstd = g_stats[BB*CC + bc];
    float4* p = (float4*)(y + (size_t)bc * HW);
    #pragma unroll
    for (int r = 0; r < 16; r++) {
        float4 v = p[r*256 + t];
        v.x = fmaxf((v.x - mean)*rstd, 0.f);
        v.y = fmaxf((v.y - mean)*rstd, 0.f);
        v.z = fmaxf((v.z - mean)*rstd, 0.f);
        v.w = fmaxf((v.w - mean)*rstd, 0.f);
        p[r*256 + t] = v;
    }
}

// ---------------------------------------------------------------------------
extern "C" void kernel_launch(void* const* d_in, const int* in_sizes, int n_in,
                              void* d_out, int out_size) {
    const float* x     = (const float*)d_in[0];
    const float* w_off = (const float*)d_in[1];
    const float* b_off = (const float*)d_in[2];
    const float* w_dcn = (const float*)d_in[3];
    // d_in[4] = b_dcn: cancelled by instance norm, unused.
    float* out = (float*)d_out;

    cudaFuncSetAttribute(k_off, cudaFuncAttributeMaxDynamicSharedMemorySize, K1_SMEM);

    k_wt<<<144, 256>>>(w_dcn);
    dim3 g1(WW/64, HH/16, BB);
    k_off<<<g1, 256, K1_SMEM>>>(x, w_off, b_off);
    k_dcn<<<dim3(2*HH, BB), 256>>>(x, out);
    k_stats<<<BB*CC, 256>>>(out);
    k_norm<<<BB*CC, 256>>>(out);
}

// round 3
// speedup vs baseline: 1.4684x; 1.4684x over previous
#include <cuda_runtime.h>
#include <math.h>
#include <stdint.h>

#define HH 128
#define WW 128
#define CC 64
#define BB 8
#define HW (HH*WW)

// scratch (device globals — no allocations allowed)
__device__ float  g_off[BB*18*HW];      // offset channels
__device__ float  g_mask[BB*9*HW];      // sigmoid(mask)
__device__ float2 g_wd[9*8*4*64];       // DCN B fragments, packed per (k,kb,tg,oc)
__device__ float2 g_wo[9*8*4*32];       // OFF B fragments (27 oc padded to 32)
__device__ float  g_sum[2*BB*CC];       // [0]: sum, [BB*CC]: sumsq

// ---------------------------------------------------------------------------
__device__ __forceinline__ uint32_t tf32u(float f){
    uint32_t u; asm("cvt.rna.tf32.f32 %0, %1;" : "=r"(u) : "f"(f)); return u;
}
__device__ __forceinline__ float tf32f(float f){ return __uint_as_float(tf32u(f)); }

__device__ __forceinline__ void mma8(float* d, const uint32_t* a, const uint32_t* b){
    asm volatile("mma.sync.aligned.m16n8k8.row.col.f32.tf32.tf32.f32 "
        "{%0,%1,%2,%3}, {%4,%5,%6,%7}, {%8,%9}, {%0,%1,%2,%3};"
        : "+f"(d[0]), "+f"(d[1]), "+f"(d[2]), "+f"(d[3])
        : "r"(a[0]), "r"(a[1]), "r"(a[2]), "r"(a[3]), "r"(b[0]), "r"(b[1]));
}

// ---------------------------------------------------------------------------
// Kernel W: pack B fragments (tf32-rounded) + zero stats accumulators
// g_wd[((k*8+kb)*4+tg)*64 + oc] = { W[oc][kb*8+tg][k], W[oc][kb*8+tg+4][k] }
// ---------------------------------------------------------------------------
__global__ void k_wt(const float* __restrict__ wd, const float* __restrict__ wo){
    int idx = blockIdx.x*256 + threadIdx.x;
    if (idx < 2*BB*CC) g_sum[idx] = 0.f;
    if (idx < 9*8*4*64){
        int oc = idx & 63, r = idx >> 6;
        int tg = r & 3;  r >>= 2;
        int kb = r & 7;  int k = r >> 3;
        int c0 = kb*8 + tg;
        g_wd[idx] = make_float2(tf32f(wd[(oc*64 + c0)*9 + k]),
                                tf32f(wd[(oc*64 + c0+4)*9 + k]));
    }
    if (idx < 9*8*4*32){
        int oc = idx & 31, r = idx >> 5;
        int tg = r & 3;  r >>= 2;
        int kb = r & 7;  int k = r >> 3;
        int c0 = kb*8 + tg;
        float v0 = (oc < 27) ? wo[(oc*64 + c0)*9 + k]   : 0.f;
        float v1 = (oc < 27) ? wo[(oc*64 + c0+4)*9 + k] : 0.f;
        g_wo[idx] = make_float2(tf32f(v0), tf32f(v1));
    }
}

// ---------------------------------------------------------------------------
// Kernel 1: offset conv 64->27 (tensor) + bias + sigmoid(mask)
// block = (row i, batch b). A = shifted x patches [128px x 64c] in SMEM,
// B = packed w_off fragments from global. Warp tile 32px x 16oc.
// ---------------------------------------------------------------------------
__global__ void __launch_bounds__(256)
k_off_t(const float* __restrict__ x, const float* __restrict__ bOff){
    __shared__ __align__(16) float s_v[64*136];

    int t = threadIdx.x, lane = t & 31, wid = t >> 5;
    int i = blockIdx.x, b = blockIdx.y;
    int tg = lane & 3, gq = lane >> 2;
    int p = t & 127, half = t >> 7;
    int px0 = (wid & 3) * 32, n0 = (wid >> 2) * 16;

    float acc[2][2][4];
    #pragma unroll
    for (int mt = 0; mt < 2; mt++)
        #pragma unroll
        for (int nt = 0; nt < 2; nt++)
            #pragma unroll
            for (int q = 0; q < 4; q++) acc[mt][nt][q] = 0.f;

    for (int k = 0; k < 9; k++){
        int ky = k/3 - 1, kx = k%3 - 1;
        int row = i + ky, col = p + kx;
        float okf = (((unsigned)row < HH) && ((unsigned)col < WW)) ? 1.f : 0.f;
        int rowc = min(max(row, 0), HH-1), colc = min(max(col, 0), WW-1);
        const float* xp = x + (((size_t)(b*CC + half*32))*HH + rowc)*WW + colc;
        #pragma unroll 8
        for (int c = 0; c < 32; c++){
            s_v[(half*32 + c)*136 + p] = okf * xp[0];
            xp += HW;
        }
        __syncthreads();

        const float2* wb = g_wo + k*1024;
        #pragma unroll
        for (int kb = 0; kb < 8; kb++){
            uint32_t afr[2][4];
            #pragma unroll
            for (int mt = 0; mt < 2; mt++){
                int pxb = px0 + mt*16 + gq;
                afr[mt][0] = tf32u(s_v[(kb*8 + tg  )*136 + pxb    ]);
                afr[mt][1] = tf32u(s_v[(kb*8 + tg  )*136 + pxb + 8]);
                afr[mt][2] = tf32u(s_v[(kb*8 + tg+4)*136 + pxb    ]);
                afr[mt][3] = tf32u(s_v[(kb*8 + tg+4)*136 + pxb + 8]);
            }
            #pragma unroll
            for (int nt = 0; nt < 2; nt++){
                float2 bw = wb[(kb*4 + tg)*32 + n0 + nt*8 + gq];
                uint32_t bfr[2] = { __float_as_uint(bw.x), __float_as_uint(bw.y) };
                mma8(acc[0][nt], afr[0], bfr);
                mma8(acc[1][nt], afr[1], bfr);
            }
        }
        __syncthreads();
    }

    // stage epilogue through SMEM (stride 132) for coalesced writes
    float* s_out = s_v;   // [32][132]
    #pragma unroll
    for (int mt = 0; mt < 2; mt++)
        #pragma unroll
        for (int nt = 0; nt < 2; nt++){
            int cA = n0 + nt*8 + 2*tg, rA = px0 + mt*16 + gq;
            s_out[ cA   *132 + rA    ] = acc[mt][nt][0];
            s_out[(cA+1)*132 + rA    ] = acc[mt][nt][1];
            s_out[ cA   *132 + rA + 8] = acc[mt][nt][2];
            s_out[(cA+1)*132 + rA + 8] = acc[mt][nt][3];
        }
    __syncthreads();

    #pragma unroll
    for (int r = 0; r < 14; r++){
        int idx = r*256 + t;
        if (idx < 27*128){
            int o = idx >> 7, px = idx & 127;
            float v = s_out[o*132 + px] + bOff[o];
            if (o < 18)
                g_off[((size_t)(b*18 + o))*HW + i*WW + px] = v;
            else
                g_mask[((size_t)(b*9 + o-18))*HW + i*WW + px] = 1.f/(1.f + __expf(-v));
        }
    }
}

// ---------------------------------------------------------------------------
// Kernel 2: deformable conv (tensor). block = (row i, batch b).
// phase 1: 128 threads compute bilinear params -> SMEM
// phase 2: gather v[64c][128px] into SMEM (4 clamped LDG per c-px)
// phase 3: mma, warp tile 32px x 32oc.  Fused stats reduction in epilogue.
// ---------------------------------------------------------------------------
__global__ void __launch_bounds__(256)
k_dcn_t(const float* __restrict__ x, float* __restrict__ out){
    __shared__ __align__(16) float s_v[64*136];
    __shared__ float s_pw[4*128];
    __shared__ int   s_pa[4*128];

    int t = threadIdx.x, lane = t & 31, wid = t >> 5;
    int i = blockIdx.x, b = blockIdx.y;
    int tg = lane & 3, gq = lane >> 2;
    int pp = t & 127, hc = (t >> 7)*32;
    int px0 = (wid & 3) * 32, n0 = (wid >> 2) * 32;

    const float* xb = x + (size_t)b*CC*HW;

    float acc[2][4][4];
    #pragma unroll
    for (int mt = 0; mt < 2; mt++)
        #pragma unroll
        for (int nt = 0; nt < 4; nt++)
            #pragma unroll
            for (int q = 0; q < 4; q++) acc[mt][nt][q] = 0.f;

    for (int k = 0; k < 9; k++){
        if (t < 128){
            int j = t;
            int ky = k/3 - 1, kx = k%3 - 1;
            size_t ofb = ((size_t)(b*18 + 2*k))*HW + i*WW + j;
            float oy = g_off[ofb], ox = g_off[ofb + HW];
            float m  = g_mask[((size_t)(b*9 + k))*HW + i*WW + j];
            float ys = (float)(i + ky) + oy;
            float xs = (float)(j + kx) + ox;
            float y0f = floorf(ys), x0f = floorf(xs);
            float wy1 = ys - y0f, wy0 = 1.f - wy1;
            float wx1 = xs - x0f, wx0 = 1.f - wx1;
            int r0 = (int)y0f, c0 = (int)x0f;
            bool vr0 = (unsigned)r0     < HH, vr1 = (unsigned)(r0+1) < HH;
            bool vc0 = (unsigned)c0     < WW, vc1 = (unsigned)(c0+1) < WW;
            int rc0 = min(max(r0,   0), HH-1), rc1 = min(max(r0+1, 0), HH-1);
            int cc0 = min(max(c0,   0), WW-1), cc1 = min(max(c0+1, 0), WW-1);
            s_pw[      j] = (vr0 && vc0) ? wy0*wx0*m : 0.f;  s_pa[      j] = rc0*WW + cc0;
            s_pw[128 + j] = (vr0 && vc1) ? wy0*wx1*m : 0.f;  s_pa[128 + j] = rc0*WW + cc1;
            s_pw[256 + j] = (vr1 && vc0) ? wy1*wx0*m : 0.f;  s_pa[256 + j] = rc1*WW + cc0;
            s_pw[384 + j] = (vr1 && vc1) ? wy1*wx1*m : 0.f;  s_pa[384 + j] = rc1*WW + cc1;
        }
        __syncthreads();
        {
            float w0 = s_pw[pp], w1 = s_pw[128+pp], w2 = s_pw[256+pp], w3 = s_pw[384+pp];
            int   a0 = s_pa[pp], a1 = s_pa[128+pp], a2 = s_pa[256+pp], a3 = s_pa[384+pp];
            const float* xp = xb + (size_t)hc*HW;
            #pragma unroll 4
            for (int c = 0; c < 32; c++){
                s_v[(hc + c)*136 + pp] = w0*xp[a0] + w1*xp[a1] + w2*xp[a2] + w3*xp[a3];
                xp += HW;
            }
        }
        __syncthreads();

        const float2* wb = g_wd + k*2048;
        #pragma unroll
        for (int kb = 0; kb < 8; kb++){
            uint32_t afr[2][4];
            #pragma unroll
            for (int mt = 0; mt < 2; mt++){
                int pxb = px0 + mt*16 + gq;
                afr[mt][0] = tf32u(s_v[(kb*8 + tg  )*136 + pxb    ]);
                afr[mt][1] = tf32u(s_v[(kb*8 + tg  )*136 + pxb + 8]);
                afr[mt][2] = tf32u(s_v[(kb*8 + tg+4)*136 + pxb    ]);
                afr[mt][3] = tf32u(s_v[(kb*8 + tg+4)*136 + pxb + 8]);
            }
            #pragma unroll
            for (int nt = 0; nt < 4; nt++){
                float2 bw = wb[(kb*4 + tg)*64 + n0 + nt*8 + gq];
                uint32_t bfr[2] = { __float_as_uint(bw.x), __float_as_uint(bw.y) };
                mma8(acc[0][nt], afr[0], bfr);
                mma8(acc[1][nt], afr[1], bfr);
            }
        }
        __syncthreads();
    }

    // epilogue: stage [64oc][132] in SMEM, then coalesced float4 stores +
    // fused per-(b,oc) sum/sumsq (b_dcn skipped: instance norm cancels it)
    float* s_out = s_v;
    #pragma unroll
    for (int mt = 0; mt < 2; mt++)
        #pragma unroll
        for (int nt = 0; nt < 4; nt++){
            int cA = n0 + nt*8 + 2*tg, rA = px0 + mt*16 + gq;
            s_out[ cA   *132 + rA    ] = acc[mt][nt][0];
            s_out[(cA+1)*132 + rA    ] = acc[mt][nt][1];
            s_out[ cA   *132 + rA + 8] = acc[mt][nt][2];
            s_out[(cA+1)*132 + rA + 8] = acc[mt][nt][3];
        }
    __syncthreads();

    #pragma unroll
    for (int r = 0; r < 8; r++){
        int oc = r*8 + wid;
        int p4 = lane*4;
        float4 v = *(float4*)&s_out[oc*132 + p4];
        *(float4*)&out[((size_t)(b*CC + oc))*HW + i*WW + p4] = v;
        float s  = (v.x + v.y) + (v.z + v.w);
        float ss = fmaf(v.x, v.x, fmaf(v.y, v.y, fmaf(v.z, v.z, v.w*v.w)));
        #pragma unroll
        for (int d = 16; d > 0; d >>= 1){
            s  += __shfl_xor_sync(0xFFFFFFFFu, s,  d);
            ss += __shfl_xor_sync(0xFFFFFFFFu, ss, d);
        }
        if (lane == 0){
            atomicAdd(&g_sum[b*CC + oc], s);
            atomicAdd(&g_sum[BB*CC + b*CC + oc], ss);
        }
    }
}

// ---------------------------------------------------------------------------
// Kernel 3: normalize + relu in place (stats were fused into k_dcn_t)
// ---------------------------------------------------------------------------
__global__ void k_norm(float* __restrict__ y){
    int bc = blockIdx.x;
    int t = threadIdx.x;
    float mean = g_sum[bc] * (1.f/16384.f);
    float var  = g_sum[BB*CC + bc] * (1.f/16384.f) - mean*mean;
    float rstd = rsqrtf(var + 1e-5f);
    float4* p = (float4*)(y + (size_t)bc * HW);
    #pragma unroll
    for (int r = 0; r < 16; r++){
        float4 v = p[r*256 + t];
        v.x = fmaxf((v.x - mean)*rstd, 0.f);
        v.y = fmaxf((v.y - mean)*rstd, 0.f);
        v.z = fmaxf((v.z - mean)*rstd, 0.f);
        v.w = fmaxf((v.w - mean)*rstd, 0.f);
        p[r*256 + t] = v;
    }
}

// ---------------------------------------------------------------------------
extern "C" void kernel_launch(void* const* d_in, const int* in_sizes, int n_in,
                              void* d_out, int out_size){
    const float* x     = (const float*)d_in[0];
    const float* w_off = (const float*)d_in[1];
    const float* b_off = (const float*)d_in[2];
    const float* w_dcn = (const float*)d_in[3];
    // d_in[4] = b_dcn: cancelled by instance norm.
    float* out = (float*)d_out;

    k_wt<<<144, 256>>>(w_dcn, w_off);
    k_off_t<<<dim3(HH, BB), 256>>>(x, b_off);
    k_dcn_t<<<dim3(HH, BB), 256>>>(x, out);
    k_norm<<<BB*CC, 256>>>(out);
}

// round 4
// speedup vs baseline: 1.5915x; 1.0838x over previous
#include <cuda_runtime.h>
#include <math.h>
#include <stdint.h>

#define HH 128
#define WW 128
#define CC 64
#define BB 8
#define HW (HH*WW)

// scratch (device globals — no allocations allowed)
__device__ float  g_off[BB*18*HW];      // offset channels
__device__ float  g_mask[BB*9*HW];      // sigmoid(mask)
__device__ float2 g_wd[9*8*4*64];       // DCN B fragments, packed per (k,kb,tg,oc)
__device__ float2 g_wo[9*8*4*32];       // OFF B fragments (27 oc padded to 32)
__device__ float  g_sum[2*BB*CC];       // [0]: sum, [BB*CC]: sumsq

// ---------------------------------------------------------------------------
__device__ __forceinline__ uint32_t tf32u(float f){
    uint32_t u; asm("cvt.rna.tf32.f32 %0, %1;" : "=r"(u) : "f"(f)); return u;
}
__device__ __forceinline__ float tf32f(float f){ return __uint_as_float(tf32u(f)); }

__device__ __forceinline__ void mma8(float* d, const uint32_t* a, const uint32_t* b){
    asm volatile("mma.sync.aligned.m16n8k8.row.col.f32.tf32.tf32.f32 "
        "{%0,%1,%2,%3}, {%4,%5,%6,%7}, {%8,%9}, {%0,%1,%2,%3};"
        : "+f"(d[0]), "+f"(d[1]), "+f"(d[2]), "+f"(d[3])
        : "r"(a[0]), "r"(a[1]), "r"(a[2]), "r"(a[3]), "r"(b[0]), "r"(b[1]));
}

// ---------------------------------------------------------------------------
// Kernel W: pack B fragments (tf32-rounded) + zero stats accumulators
// ---------------------------------------------------------------------------
__global__ void k_wt(const float* __restrict__ wd, const float* __restrict__ wo){
    int idx = blockIdx.x*256 + threadIdx.x;
    if (idx < 2*BB*CC) g_sum[idx] = 0.f;
    if (idx < 9*8*4*64){
        int oc = idx & 63, r = idx >> 6;
        int tg = r & 3;  r >>= 2;
        int kb = r & 7;  int k = r >> 3;
        int c0 = kb*8 + tg;
        g_wd[idx] = make_float2(tf32f(wd[(oc*64 + c0)*9 + k]),
                                tf32f(wd[(oc*64 + c0+4)*9 + k]));
    }
    if (idx < 9*8*4*32){
        int oc = idx & 31, r = idx >> 5;
        int tg = r & 3;  r >>= 2;
        int kb = r & 7;  int k = r >> 3;
        int c0 = kb*8 + tg;
        float v0 = (oc < 27) ? wo[(oc*64 + c0)*9 + k]   : 0.f;
        float v1 = (oc < 27) ? wo[(oc*64 + c0+4)*9 + k] : 0.f;
        g_wo[idx] = make_float2(tf32f(v0), tf32f(v1));
    }
}

// ---------------------------------------------------------------------------
// Kernel 1: offset conv 64->27 (tensor) + bias + sigmoid(mask)
// block = (row i, batch b). Stage x rows i-1..i+1 (tf32-rounded) ONCE into
// SMEM [64c][3r][136]; all 9 taps read shifted windows. Warp tile 32px x 16oc.
// ---------------------------------------------------------------------------
#define OFF_CS 408                      // 3*136 floats per channel
#define OFF_SMEM (64*OFF_CS*4)          // 104448 bytes

__global__ void __launch_bounds__(256)
k_off_t(const float* __restrict__ x, const float* __restrict__ bOff){
    extern __shared__ __align__(16) float sm[];

    int t = threadIdx.x, lane = t & 31, wid = t >> 5;
    int i = blockIdx.x, b = blockIdx.y;
    int tg = lane & 3, gq = lane >> 2;
    int px0 = (wid & 3) * 32, n0 = (wid >> 2) * 16;

    // stage x (tf32-rounded bits stored as float)
    for (int idx = t; idx < 64*OFF_CS; idx += 256){
        int c = idx / OFF_CS, rem = idx - c*OFF_CS;
        int r = rem / 136, col = rem - r*136;
        int gi = i - 1 + r, gj = col - 1;
        float v = 0.f;
        if ((unsigned)gi < HH && (unsigned)(col-1) < WW && col < 130)
            v = x[(((size_t)(b*CC + c))*HH + gi)*WW + gj];
        sm[idx] = tf32f(v);
    }
    __syncthreads();

    float acc[2][2][4];
    #pragma unroll
    for (int mt = 0; mt < 2; mt++)
        #pragma unroll
        for (int nt = 0; nt < 2; nt++)
            #pragma unroll
            for (int q = 0; q < 4; q++) acc[mt][nt][q] = 0.f;

    #pragma unroll 1
    for (int k = 0; k < 9; k++){
        int base = (k/3)*136 + (k%3);        // (ky+1)*136 + (kx+1) - 1 + 1
        const float2* wb = g_wo + k*1024;
        #pragma unroll
        for (int kb = 0; kb < 8; kb++){
            uint32_t afr[2][4];
            #pragma unroll
            for (int mt = 0; mt < 2; mt++){
                int pxb = base + px0 + mt*16 + gq;
                const float* r0 = sm + (kb*8 + tg)*OFF_CS;
                const float* r4 = sm + (kb*8 + tg+4)*OFF_CS;
                afr[mt][0] = __float_as_uint(r0[pxb]);
                afr[mt][1] = __float_as_uint(r0[pxb + 8]);
                afr[mt][2] = __float_as_uint(r4[pxb]);
                afr[mt][3] = __float_as_uint(r4[pxb + 8]);
            }
            #pragma unroll
            for (int nt = 0; nt < 2; nt++){
                float2 bw = wb[(kb*4 + tg)*32 + n0 + nt*8 + gq];
                uint32_t bfr[2] = { __float_as_uint(bw.x), __float_as_uint(bw.y) };
                mma8(acc[0][nt], afr[0], bfr);
                mma8(acc[1][nt], afr[1], bfr);
            }
        }
    }
    __syncthreads();

    // stage epilogue through SMEM (stride 132) for coalesced writes
    float* s_out = sm;   // [32][132]
    #pragma unroll
    for (int mt = 0; mt < 2; mt++)
        #pragma unroll
        for (int nt = 0; nt < 2; nt++){
            int cA = n0 + nt*8 + 2*tg, rA = px0 + mt*16 + gq;
            s_out[ cA   *132 + rA    ] = acc[mt][nt][0];
            s_out[(cA+1)*132 + rA    ] = acc[mt][nt][1];
            s_out[ cA   *132 + rA + 8] = acc[mt][nt][2];
            s_out[(cA+1)*132 + rA + 8] = acc[mt][nt][3];
        }
    __syncthreads();

    #pragma unroll
    for (int r = 0; r < 14; r++){
        int idx = r*256 + t;
        if (idx < 27*128){
            int o = idx >> 7, px = idx & 127;
            float v = s_out[o*132 + px] + bOff[o];
            if (o < 18)
                g_off[((size_t)(b*18 + o))*HW + i*WW + px] = v;
            else
                g_mask[((size_t)(b*9 + o-18))*HW + i*WW + px] = 1.f/(1.f + __expf(-v));
        }
    }
}

// ---------------------------------------------------------------------------
// Kernel 2: deformable conv (tensor). block = (row i, batch b).
// Per tap: [t<128: bilinear params | t>=128: stage B into dbl-buffered SMEM]
// -> sync -> gather v (tf32-rounded) -> sync -> MMA (A+B both from SMEM).
// Fused per-(b,oc) stats reduction in epilogue.
// ---------------------------------------------------------------------------
#define DV  0                      // s_v: 64*136 floats (tf32 bits)
#define DWB 8704                   // B bufs: 2 * (2 planes * 32 rows * 72)
#define DWBSZ 4608                 // floats per buffer
#define DPW (8704 + 2*DWBSZ)       // 4*128
#define DPA (DPW + 512)            // 4*128
#define DCN_SMEM ((DPA + 512)*4)   // 75776 bytes

__global__ void __launch_bounds__(256)
k_dcn_t(const float* __restrict__ x, float* __restrict__ out){
    extern __shared__ __align__(16) float sm[];
    float* s_v  = sm;
    float* s_pw = sm + DPW;
    int*   s_pa = (int*)(sm + DPA);

    int t = threadIdx.x, lane = t & 31, wid = t >> 5;
    int i = blockIdx.x, b = blockIdx.y;
    int tg = lane & 3, gq = lane >> 2;
    int pp = t & 127, hc = (t >> 7)*32;
    int px0 = (wid & 3) * 32, n0 = (wid >> 2) * 32;

    const float* xb = x + (size_t)b*CC*HW;

    float acc[2][4][4];
    #pragma unroll
    for (int mt = 0; mt < 2; mt++)
        #pragma unroll
        for (int nt = 0; nt < 4; nt++)
            #pragma unroll
            for (int q = 0; q < 4; q++) acc[mt][nt][q] = 0.f;

    #pragma unroll 1
    for (int k = 0; k < 9; k++){
        float* swb = sm + DWB + (k & 1)*DWBSZ;
        if (t < 128){
            int j = t;
            int ky = k/3 - 1, kx = k%3 - 1;
            size_t ofb = ((size_t)(b*18 + 2*k))*HW + i*WW + j;
            float oy = g_off[ofb], ox = g_off[ofb + HW];
            float m  = g_mask[((size_t)(b*9 + k))*HW + i*WW + j];
            float ys = (float)(i + ky) + oy;
            float xs = (float)(j + kx) + ox;
            float y0f = floorf(ys), x0f = floorf(xs);
            float wy1 = ys - y0f, wy0 = 1.f - wy1;
            float wx1 = xs - x0f, wx0 = 1.f - wx1;
            int r0 = (int)y0f, c0 = (int)x0f;
            bool vr0 = (unsigned)r0     < HH, vr1 = (unsigned)(r0+1) < HH;
            bool vc0 = (unsigned)c0     < WW, vc1 = (unsigned)(c0+1) < WW;
            int rc0 = min(max(r0,   0), HH-1), rc1 = min(max(r0+1, 0), HH-1);
            int cc0 = min(max(c0,   0), WW-1), cc1 = min(max(c0+1, 0), WW-1);
            s_pw[      j] = (vr0 && vc0) ? wy0*wx0*m : 0.f;  s_pa[      j] = rc0*WW + cc0;
            s_pw[128 + j] = (vr0 && vc1) ? wy0*wx1*m : 0.f;  s_pa[128 + j] = rc0*WW + cc1;
            s_pw[256 + j] = (vr1 && vc0) ? wy1*wx0*m : 0.f;  s_pa[256 + j] = rc1*WW + cc0;
            s_pw[384 + j] = (vr1 && vc1) ? wy1*wx1*m : 0.f;  s_pa[384 + j] = rc1*WW + cc1;
        } else {
            // stage B tap k: g_wd float2 (kb,tg,oc) -> planes [32 rows][72]
            int tt = t - 128;
            const float2* src = g_wd + (size_t)k*2048;
            #pragma unroll
            for (int r = 0; r < 16; r++){
                int j = r*128 + tt;            // j = row*64 + oc
                int row = j >> 6, oc = j & 63;
                float2 v = src[j];
                swb[row*72 + oc] = v.x;
                swb[DWBSZ/2 + row*72 + oc] = v.y;
            }
        }
        __syncthreads();
        {
            float w0 = s_pw[pp], w1 = s_pw[128+pp], w2 = s_pw[256+pp], w3 = s_pw[384+pp];
            int   a0 = s_pa[pp], a1 = s_pa[128+pp], a2 = s_pa[256+pp], a3 = s_pa[384+pp];
            const float* xp = xb + (size_t)hc*HW;
            #pragma unroll 4
            for (int c = 0; c < 32; c++){
                float v = w0*xp[a0] + w1*xp[a1] + w2*xp[a2] + w3*xp[a3];
                s_v[(hc + c)*136 + pp] = tf32f(v);
                xp += HW;
            }
        }
        __syncthreads();

        #pragma unroll
        for (int kb = 0; kb < 8; kb++){
            uint32_t afr[2][4];
            #pragma unroll
            for (int mt = 0; mt < 2; mt++){
                int pxb = px0 + mt*16 + gq;
                const float* r0 = s_v + (kb*8 + tg)*136;
                const float* r4 = s_v + (kb*8 + tg+4)*136;
                afr[mt][0] = __float_as_uint(r0[pxb]);
                afr[mt][1] = __float_as_uint(r0[pxb + 8]);
                afr[mt][2] = __float_as_uint(r4[pxb]);
                afr[mt][3] = __float_as_uint(r4[pxb + 8]);
            }
            const float* b0p = swb + (kb*4 + tg)*72;
            const float* b1p = b0p + DWBSZ/2;
            #pragma unroll
            for (int nt = 0; nt < 4; nt++){
                int oc = n0 + nt*8 + gq;
                uint32_t bfr[2] = { __float_as_uint(b0p[oc]), __float_as_uint(b1p[oc]) };
                mma8(acc[0][nt], afr[0], bfr);
                mma8(acc[1][nt], afr[1], bfr);
            }
        }
    }
    __syncthreads();

    // epilogue: stage [64oc][132] in SMEM -> coalesced float4 stores +
    // fused per-(b,oc) sum/sumsq (b_dcn skipped: instance norm cancels it)
    float* s_out = sm;
    #pragma unroll
    for (int mt = 0; mt < 2; mt++)
        #pragma unroll
        for (int nt = 0; nt < 4; nt++){
            int cA = n0 + nt*8 + 2*tg, rA = px0 + mt*16 + gq;
            s_out[ cA   *132 + rA    ] = acc[mt][nt][0];
            s_out[(cA+1)*132 + rA    ] = acc[mt][nt][1];
            s_out[ cA   *132 + rA + 8] = acc[mt][nt][2];
            s_out[(cA+1)*132 + rA + 8] = acc[mt][nt][3];
        }
    __syncthreads();

    #pragma unroll
    for (int r = 0; r < 8; r++){
        int oc = r*8 + wid;
        int p4 = lane*4;
        float4 v = *(float4*)&s_out[oc*132 + p4];
        *(float4*)&out[((size_t)(b*CC + oc))*HW + i*WW + p4] = v;
        float s  = (v.x + v.y) + (v.z + v.w);
        float ss = fmaf(v.x, v.x, fmaf(v.y, v.y, fmaf(v.z, v.z, v.w*v.w)));
        #pragma unroll
        for (int d = 16; d > 0; d >>= 1){
            s  += __shfl_xor_sync(0xFFFFFFFFu, s,  d);
            ss += __shfl_xor_sync(0xFFFFFFFFu, ss, d);
        }
        if (lane == 0){
            atomicAdd(&g_sum[b*CC + oc], s);
            atomicAdd(&g_sum[BB*CC + b*CC + oc], ss);
        }
    }
}

// ---------------------------------------------------------------------------
// Kernel 3: normalize + relu in place (stats fused into k_dcn_t)
// ---------------------------------------------------------------------------
__global__ void k_norm(float* __restrict__ y){
    int bc = blockIdx.x;
    int t = threadIdx.x;
    float mean = g_sum[bc] * (1.f/16384.f);
    float var  = g_sum[BB*CC + bc] * (1.f/16384.f) - mean*mean;
    float rstd = rsqrtf(var + 1e-5f);
    float4* p = (float4*)(y + (size_t)bc * HW);
    #pragma unroll
    for (int r = 0; r < 16; r++){
        float4 v = p[r*256 + t];
        v.x = fmaxf((v.x - mean)*rstd, 0.f);
        v.y = fmaxf((v.y - mean)*rstd, 0.f);
        v.z = fmaxf((v.z - mean)*rstd, 0.f);
        v.w = fmaxf((v.w - mean)*rstd, 0.f);
        p[r*256 + t] = v;
    }
}

// ---------------------------------------------------------------------------
extern "C" void kernel_launch(void* const* d_in, const int* in_sizes, int n_in,
                              void* d_out, int out_size){
    const float* x     = (const float*)d_in[0];
    const float* w_off = (const float*)d_in[1];
    const float* b_off = (const float*)d_in[2];
    const float* w_dcn = (const float*)d_in[3];
    // d_in[4] = b_dcn: cancelled by instance norm.
    float* out = (float*)d_out;

    cudaFuncSetAttribute(k_off_t, cudaFuncAttributeMaxDynamicSharedMemorySize, OFF_SMEM);
    cudaFuncSetAttribute(k_dcn_t, cudaFuncAttributeMaxDynamicSharedMemorySize, DCN_SMEM);

    k_wt<<<144, 256>>>(w_dcn, w_off);
    k_off_t<<<dim3(HH, BB), 256, OFF_SMEM>>>(x, b_off);
    k_dcn_t<<<dim3(HH, BB), 256, DCN_SMEM>>>(x, out);
    k_norm<<<BB*CC, 256>>>(out);
}